// round 1
// baseline (speedup 1.0000x reference)
#include <cuda_runtime.h>
#include <math.h>

#define QLEN 1024
#define MLEN 1024
#define KLEN 2048
#define BSZ  4
#define DM   1024
#define NH   16
#define DH   64
#define SCALE 0.125f

// Scratch (device globals; no allocation allowed)
__device__ float g_Q [(size_t)BSZ*NH*QLEN*DH];   // [b][n][i][d]
__device__ float g_K [(size_t)BSZ*NH*KLEN*DH];   // [b][n][j][d]
__device__ float g_V [(size_t)BSZ*NH*KLEN*DH];   // [b][n][j][d]
__device__ float g_R [(size_t)NH*KLEN*DH];       // [n][p][d]
__device__ float g_AV[(size_t)QLEN*BSZ*DM];      // [i][b][n*64+d]
__device__ float g_AO[(size_t)QLEN*BSZ*DM];      // [i][b][c]

// ---------------------------------------------------------------------------
// Generic C = A @ B^T SGEMM, 128x128 tile, BK=8, 256 threads, 8x8 per thread.
// MODE 0: A = virtual concat(mems, w) rows [t*BSZ+b], B = qkv_w; scatter to Q/K/V
// MODE 1: A = r, B = r_w; scatter to g_R
// MODE 2: A = g_AV, B = o_w; write g_AO
// ---------------------------------------------------------------------------
template<int MODE>
__global__ void __launch_bounds__(256) sgemm_kernel(
    const float* __restrict__ A, const float* __restrict__ B,
    const float* __restrict__ w, const float* __restrict__ mems, int K)
{
    __shared__ float As[8][128];
    __shared__ float Bs[8][128];
    const int tid = threadIdx.x;
    const int m0 = blockIdx.y * 128;
    const int n0 = blockIdx.x * 128;
    const int lrow = tid >> 1;          // 0..127
    const int lcol = (tid & 1) * 4;     // 0 or 4

    const float* aptr;
    if (MODE == 0) {
        int grow = m0 + lrow;
        int t = grow >> 2, b = grow & 3;
        aptr = (t < MLEN) ? (mems + ((size_t)t * BSZ + b) * DM)
                          : (w    + ((size_t)(t - MLEN) * BSZ + b) * DM);
    } else if (MODE == 2) {
        aptr = g_AV + (size_t)(m0 + lrow) * K;
    } else {
        aptr = A + (size_t)(m0 + lrow) * K;
    }
    const float* bptr = B + (size_t)(n0 + lrow) * K;

    const int tr = tid >> 4;   // 0..15
    const int tc = tid & 15;   // 0..15

    float acc[8][8];
#pragma unroll
    for (int i = 0; i < 8; i++)
#pragma unroll
        for (int j = 0; j < 8; j++) acc[i][j] = 0.f;

    for (int k0 = 0; k0 < K; k0 += 8) {
        float4 av = *(const float4*)(aptr + k0 + lcol);
        float4 bv = *(const float4*)(bptr + k0 + lcol);
        As[lcol + 0][lrow] = av.x; As[lcol + 1][lrow] = av.y;
        As[lcol + 2][lrow] = av.z; As[lcol + 3][lrow] = av.w;
        Bs[lcol + 0][lrow] = bv.x; Bs[lcol + 1][lrow] = bv.y;
        Bs[lcol + 2][lrow] = bv.z; Bs[lcol + 3][lrow] = bv.w;
        __syncthreads();
#pragma unroll
        for (int k = 0; k < 8; k++) {
            float a[8], bb[8];
            *(float4*)(a)      = *(const float4*)&As[k][tr * 4];
            *(float4*)(a + 4)  = *(const float4*)&As[k][tr * 4 + 64];
            *(float4*)(bb)     = *(const float4*)&Bs[k][tc * 4];
            *(float4*)(bb + 4) = *(const float4*)&Bs[k][tc * 4 + 64];
#pragma unroll
            for (int i = 0; i < 8; i++)
#pragma unroll
                for (int j = 0; j < 8; j++) acc[i][j] += a[i] * bb[j];
        }
        __syncthreads();
    }

#pragma unroll
    for (int i = 0; i < 8; i++) {
        int gr = m0 + ((i < 4) ? tr * 4 + i : 64 + tr * 4 + i - 4);
#pragma unroll
        for (int j = 0; j < 8; j++) {
            int gc = n0 + ((j < 4) ? tc * 4 + j : 64 + tc * 4 + j - 4);
            float v = acc[i][j];
            if (MODE == 0) {
                int part = gc >> 10, hn = (gc >> 6) & 15, d = gc & 63;
                int t = gr >> 2, b = gr & 3;
                if (part == 0) {
                    if (t >= MLEN)
                        g_Q[(((size_t)(b * NH + hn)) * QLEN + (t - MLEN)) * DH + d] = v;
                } else if (part == 1) {
                    g_K[(((size_t)(b * NH + hn)) * KLEN + t) * DH + d] = v;
                } else {
                    g_V[(((size_t)(b * NH + hn)) * KLEN + t) * DH + d] = v;
                }
            } else if (MODE == 1) {
                int hn = gc >> 6, d = gc & 63;
                g_R[((size_t)hn * KLEN + gr) * DH + d] = v;
            } else {
                g_AO[(size_t)gr * DM + gc] = v;
            }
        }
    }
}

// ---------------------------------------------------------------------------
// Fused attention: per block = 64 queries x one (b,n).
// S[i,j] = Qu_i·K_j + Qv_i·R[j+1023-i], causal mask j > MLEN+i, online softmax,
// O += P @ V. Rel-shift handled by the shifted R slab (rows rbase..rbase+127).
// Thread map: il = tid/4 (query row), quad member qd = tid%4 owns 16 j's for S
// and 16 d's for O. Softmax reductions are quad-local shuffles.
// ---------------------------------------------------------------------------
__global__ void __launch_bounds__(256) attn_kernel(
    const float* __restrict__ rwb, const float* __restrict__ rrb)
{
    extern __shared__ float sm[];
    float* Qu = sm;                  // [64][68]
    float* Qv = Qu + 64 * 68;        // [64][68]
    float* Ks = Qv + 64 * 68;        // [d][j]  [64][68]
    float* Rs = Ks + 64 * 68;        // [d][rr] [64][132]
    float* Vs = Rs + 64 * 132;       // [j][d]  [64][68]
    float* Ps = Vs + 64 * 68;        // [i][j]  [64][68]

    const int i0 = blockIdx.x * 64;
    const int bn = blockIdx.y;
    const int b = bn >> 4, n = bn & 15;
    const int tid = threadIdx.x;

    const float* Qg = g_Q + ((size_t)bn * QLEN + i0) * DH;
    const float* Kg = g_K + (size_t)bn * KLEN * DH;
    const float* Vg = g_V + (size_t)bn * KLEN * DH;
    const float* Rg = g_R + (size_t)n * KLEN * DH;

    // Load Q tile, fold biases and softmax scale
    for (int vv = tid; vv < 64 * 64 / 4; vv += 256) {
        int idx = vv * 4, i = idx >> 6, d = idx & 63;
        float4 q  = *(const float4*)(Qg + i * DH + d);
        float4 u  = *(const float4*)(rwb + n * DH + d);
        float4 vb = *(const float4*)(rrb + n * DH + d);
        Qu[i*68+d+0] = (q.x+u.x)*SCALE;  Qu[i*68+d+1] = (q.y+u.y)*SCALE;
        Qu[i*68+d+2] = (q.z+u.z)*SCALE;  Qu[i*68+d+3] = (q.w+u.w)*SCALE;
        Qv[i*68+d+0] = (q.x+vb.x)*SCALE; Qv[i*68+d+1] = (q.y+vb.y)*SCALE;
        Qv[i*68+d+2] = (q.z+vb.z)*SCALE; Qv[i*68+d+3] = (q.w+vb.w)*SCALE;
    }

    const int il = tid >> 2;     // local query row
    const int qd = tid & 3;      // quad member
    const int jb = qd * 16;      // j range base (scores)
    const int d0 = qd * 16;      // d range base (output)
    const int ig = i0 + il;

    float m = -1e30f, l = 0.f;
    float O[16];
#pragma unroll
    for (int x = 0; x < 16; x++) O[x] = 0.f;

    const int njt = (MLEN + i0 + 63) / 64 + 1;   // j-tiles needed (causal)

    for (int jt = 0; jt < njt; jt++) {
        const int j0 = jt * 64;
        const int rbase = j0 - i0 + (QLEN - 64);  // >= 0 always
        __syncthreads();
        // K (transposed to [d][j]) and V tiles
        for (int vv = tid; vv < 64 * 64 / 4; vv += 256) {
            int idx = vv * 4, j = idx >> 6, d = idx & 63;
            float4 kv = *(const float4*)(Kg + (size_t)(j0 + j) * DH + d);
            Ks[(d+0)*68+j] = kv.x; Ks[(d+1)*68+j] = kv.y;
            Ks[(d+2)*68+j] = kv.z; Ks[(d+3)*68+j] = kv.w;
            float4 vvv = *(const float4*)(Vg + (size_t)(j0 + j) * DH + d);
            *(float4*)&Vs[j*68+d] = vvv;
        }
        // R slab [d][rr], 128 rows starting at rbase (clamped; OOB rows are masked)
        for (int vv = tid; vv < 128 * 64 / 4; vv += 256) {
            int idx = vv * 4, rr = idx >> 6, d = idx & 63;
            int row = rbase + rr; row = row > KLEN - 1 ? KLEN - 1 : row;
            float4 rv = *(const float4*)(Rg + (size_t)row * DH + d);
            Rs[(d+0)*132+rr] = rv.x; Rs[(d+1)*132+rr] = rv.y;
            Rs[(d+2)*132+rr] = rv.z; Rs[(d+3)*132+rr] = rv.w;
        }
        __syncthreads();

        // Scores: S[x] = Qu·K + Qv·R(shifted)
        float S[16];
#pragma unroll
        for (int x = 0; x < 16; x++) S[x] = 0.f;
        const int roff = jb + 63 - il;       // rr for x=0
        const float* qup = Qu + il * 68;
        const float* qvp = Qv + il * 68;
#pragma unroll 4
        for (int d = 0; d < 64; d++) {
            float qu = qup[d], qv = qvp[d];
            const float* kp = Ks + d * 68 + jb;
            const float* rp = Rs + d * 132 + roff;
#pragma unroll
            for (int x = 0; x < 16; x++) S[x] += qu * kp[x] + qv * rp[x];
        }

        // Mask + online softmax (quad-local)
        float tmax = -1e30f;
#pragma unroll
        for (int x = 0; x < 16; x++) {
            if (j0 + jb + x > MLEN + ig) S[x] = -1e30f;
            tmax = fmaxf(tmax, S[x]);
        }
        tmax = fmaxf(tmax, __shfl_xor_sync(0xffffffffu, tmax, 1));
        tmax = fmaxf(tmax, __shfl_xor_sync(0xffffffffu, tmax, 2));
        float mnew = fmaxf(m, tmax);
        float corr = __expf(m - mnew);
        float ps = 0.f;
#pragma unroll
        for (int x = 0; x < 16; x++) { float p = __expf(S[x] - mnew); S[x] = p; ps += p; }
        ps += __shfl_xor_sync(0xffffffffu, ps, 1);
        ps += __shfl_xor_sync(0xffffffffu, ps, 2);
        l = l * corr + ps;
        m = mnew;
#pragma unroll
        for (int x = 0; x < 16; x++) O[x] *= corr;

        // publish P row segment, then accumulate P @ V (quad-local, warp-sync)
#pragma unroll
        for (int x = 0; x < 16; x += 4)
            *(float4*)&Ps[il*68 + jb + x] = make_float4(S[x], S[x+1], S[x+2], S[x+3]);
        __syncwarp();
#pragma unroll 2
        for (int j = 0; j < 64; j++) {
            float p = Ps[il*68 + j];
            const float* vp = Vs + j * 68 + d0;
#pragma unroll
            for (int x = 0; x < 16; x++) O[x] += p * vp[x];
        }
    }

    const float inv = 1.f / l;
    float* op = g_AV + ((size_t)ig * BSZ + b) * DM + n * DH + d0;
#pragma unroll
    for (int x = 0; x < 16; x += 4)
        *(float4*)&op[x] = make_float4(O[x]*inv, O[x+1]*inv, O[x+2]*inv, O[x+3]*inv);
}

// ---------------------------------------------------------------------------
// Residual + LayerNorm: out = LN(w + attn_out) * g + b; one block per row.
// ---------------------------------------------------------------------------
__global__ void __launch_bounds__(256) ln_kernel(
    const float* __restrict__ w, const float* __restrict__ g,
    const float* __restrict__ beta, float* __restrict__ out)
{
    const int row = blockIdx.x;
    const float* ao = g_AO + (size_t)row * DM;
    const float* wr = w    + (size_t)row * DM;
    const int tid = threadIdx.x;
    float x[4];
    float s = 0.f, ss = 0.f;
#pragma unroll
    for (int v = 0; v < 4; v++) {
        int c = tid + v * 256;
        float val = wr[c] + ao[c];
        x[v] = val; s += val; ss += val * val;
    }
#pragma unroll
    for (int o = 16; o; o >>= 1) {
        s  += __shfl_xor_sync(0xffffffffu, s,  o);
        ss += __shfl_xor_sync(0xffffffffu, ss, o);
    }
    __shared__ float sA[8], sB[8];
    int wid = tid >> 5, lane = tid & 31;
    if (lane == 0) { sA[wid] = s; sB[wid] = ss; }
    __syncthreads();
    if (wid == 0) {
        s  = (lane < 8) ? sA[lane] : 0.f;
        ss = (lane < 8) ? sB[lane] : 0.f;
#pragma unroll
        for (int o = 4; o; o >>= 1) {
            s  += __shfl_xor_sync(0xffffffffu, s,  o);
            ss += __shfl_xor_sync(0xffffffffu, ss, o);
        }
        if (lane == 0) { sA[0] = s; sB[0] = ss; }
    }
    __syncthreads();
    const float mu  = sA[0] * (1.f / DM);
    const float var = sB[0] * (1.f / DM) - mu * mu;
    const float rstd = rsqrtf(var + 1e-5f);
#pragma unroll
    for (int v = 0; v < 4; v++) {
        int c = tid + v * 256;
        out[(size_t)row * DM + c] = (x[v] - mu) * rstd * g[c] + beta[c];
    }
}

extern "C" void kernel_launch(void* const* d_in, const int* in_sizes, int n_in,
                              void* d_out, int out_size)
{
    const float* w     = (const float*)d_in[0];
    const float* r     = (const float*)d_in[1];
    const float* mems  = (const float*)d_in[2];
    // d_in[3] = attn_mask: analytic (j > MLEN + i), never read
    const float* qkv_w = (const float*)d_in[4];
    const float* r_w   = (const float*)d_in[5];
    const float* o_w   = (const float*)d_in[6];
    const float* rwb   = (const float*)d_in[7];
    const float* rrb   = (const float*)d_in[8];
    const float* ln_g  = (const float*)d_in[9];
    const float* ln_b  = (const float*)d_in[10];
    float* out = (float*)d_out;

    // 1) QKV projection over concat(mems, w)
    sgemm_kernel<0><<<dim3(3072 / 128, (KLEN * BSZ) / 128), 256>>>(
        nullptr, qkv_w, w, mems, DM);
    // 2) relative-position keys
    sgemm_kernel<1><<<dim3(DM / 128, KLEN / 128), 256>>>(
        r, r_w, nullptr, nullptr, DM);
    // 3) fused attention
    const int shmem = (64 * 68 * 5 + 64 * 132) * 4;  // 120832 B
    cudaFuncSetAttribute(attn_kernel, cudaFuncAttributeMaxDynamicSharedMemorySize, shmem);
    attn_kernel<<<dim3(QLEN / 64, BSZ * NH), 256, shmem>>>(rwb, rrb);
    // 4) output projection
    sgemm_kernel<2><<<dim3(DM / 128, (QLEN * BSZ) / 128), 256>>>(
        nullptr, o_w, nullptr, nullptr, DM);
    // 5) residual + LayerNorm
    ln_kernel<<<QLEN * BSZ, 256>>>(w, ln_g, ln_b, out);
}

// round 3
// speedup vs baseline: 1.1699x; 1.1699x over previous
#include <cuda_runtime.h>
#include <math.h>

#define QLEN 1024
#define MLEN 1024
#define KLEN 2048
#define BSZ  4
#define DM   1024
#define NH   16
#define DH   64
#define SCALE 0.125f

// Scratch (device globals; no allocation allowed)
__device__ float g_Q [(size_t)BSZ*NH*QLEN*DH];   // [b][n][i][d]
__device__ float g_K [(size_t)BSZ*NH*KLEN*DH];   // [b][n][j][d]
__device__ float g_V [(size_t)BSZ*NH*KLEN*DH];   // [b][n][j][d]
__device__ float g_R [(size_t)NH*KLEN*DH];       // [n][p][d]
__device__ float g_AV[(size_t)QLEN*BSZ*DM];      // [i][b][n*64+d]
__device__ float g_AO[(size_t)QLEN*BSZ*DM];      // [i][b][c]

// ---------------------------------------------------------------------------
// Generic C = A @ B^T SGEMM, 128x128 tile, BK=8, 256 threads, 8x8 per thread,
// with register prefetch of the next K-slab.
// MODE 0: A = virtual concat(mems, w) rows [t*BSZ+b], B = qkv_w; scatter to Q/K/V
// MODE 1: A = r, B = r_w; scatter to g_R
// MODE 2: A = g_AV, B = o_w; write g_AO
// ---------------------------------------------------------------------------
template<int MODE>
__global__ void __launch_bounds__(256) sgemm_kernel(
    const float* __restrict__ A, const float* __restrict__ B,
    const float* __restrict__ w, const float* __restrict__ mems, int K)
{
    __shared__ float As[8][128];
    __shared__ float Bs[8][128];
    const int tid = threadIdx.x;
    const int m0 = blockIdx.y * 128;
    const int n0 = blockIdx.x * 128;
    const int lrow = tid >> 1;          // 0..127
    const int lcol = (tid & 1) * 4;     // 0 or 4

    const float* aptr;
    if (MODE == 0) {
        int grow = m0 + lrow;
        int t = grow >> 2, b = grow & 3;
        aptr = (t < MLEN) ? (mems + ((size_t)t * BSZ + b) * DM)
                          : (w    + ((size_t)(t - MLEN) * BSZ + b) * DM);
    } else if (MODE == 2) {
        aptr = g_AV + (size_t)(m0 + lrow) * K;
    } else {
        aptr = A + (size_t)(m0 + lrow) * K;
    }
    const float* bptr = B + (size_t)(n0 + lrow) * K;

    const int tr = tid >> 4;   // 0..15
    const int tc = tid & 15;   // 0..15

    float acc[8][8];
#pragma unroll
    for (int i = 0; i < 8; i++)
#pragma unroll
        for (int j = 0; j < 8; j++) acc[i][j] = 0.f;

    float4 av = *(const float4*)(aptr + lcol);
    float4 bv = *(const float4*)(bptr + lcol);

    for (int k0 = 0; k0 < K; k0 += 8) {
        As[lcol + 0][lrow] = av.x; As[lcol + 1][lrow] = av.y;
        As[lcol + 2][lrow] = av.z; As[lcol + 3][lrow] = av.w;
        Bs[lcol + 0][lrow] = bv.x; Bs[lcol + 1][lrow] = bv.y;
        Bs[lcol + 2][lrow] = bv.z; Bs[lcol + 3][lrow] = bv.w;
        __syncthreads();
        if (k0 + 8 < K) {
            av = *(const float4*)(aptr + k0 + 8 + lcol);
            bv = *(const float4*)(bptr + k0 + 8 + lcol);
        }
#pragma unroll
        for (int k = 0; k < 8; k++) {
            float a[8], bb[8];
            *(float4*)(a)      = *(const float4*)&As[k][tr * 4];
            *(float4*)(a + 4)  = *(const float4*)&As[k][tr * 4 + 64];
            *(float4*)(bb)     = *(const float4*)&Bs[k][tc * 4];
            *(float4*)(bb + 4) = *(const float4*)&Bs[k][tc * 4 + 64];
#pragma unroll
            for (int i = 0; i < 8; i++)
#pragma unroll
                for (int j = 0; j < 8; j++) acc[i][j] += a[i] * bb[j];
        }
        __syncthreads();
    }

#pragma unroll
    for (int i = 0; i < 8; i++) {
        int gr = m0 + ((i < 4) ? tr * 4 + i : 64 + tr * 4 + i - 4);
#pragma unroll
        for (int j = 0; j < 8; j++) {
            int gc = n0 + ((j < 4) ? tc * 4 + j : 64 + tc * 4 + j - 4);
            float v = acc[i][j];
            if (MODE == 0) {
                int part = gc >> 10, hn = (gc >> 6) & 15, d = gc & 63;
                int t = gr >> 2, b = gr & 3;
                if (part == 0) {
                    if (t >= MLEN)
                        g_Q[(((size_t)(b * NH + hn)) * QLEN + (t - MLEN)) * DH + d] = v;
                } else if (part == 1) {
                    g_K[(((size_t)(b * NH + hn)) * KLEN + t) * DH + d] = v;
                } else {
                    g_V[(((size_t)(b * NH + hn)) * KLEN + t) * DH + d] = v;
                }
            } else if (MODE == 1) {
                int hn = gc >> 6, d = gc & 63;
                g_R[((size_t)hn * KLEN + gr) * DH + d] = v;
            } else {
                g_AO[(size_t)gr * DM + gc] = v;
            }
        }
    }
}

// ---------------------------------------------------------------------------
// Fused attention v2. Per block: 64 queries x one (b,n). Per 64-wide j-tile:
//   stage1: BDhat[i][p] = Qv_i . Rslab[p]  (regular 64x128x64 GEMM, register
//           outer-product blocking -> FMA-bound, shared buffer Bh)
//   stage2: S[i][j] = Qu_i . K_j  +  Bh[i][j+63-i]   (single scalar gather
//           applies the Transformer-XL rel-shift)
//   mask (j_glob > MLEN+i_glob), online softmax (quad-local), O += P @ V.
// Ps aliases Bh (row il only touched by the warp owning il; __syncwarp
// separates the Bh gather from the Ps overwrite).
// ---------------------------------------------------------------------------
__global__ void __launch_bounds__(256) attn_kernel(
    const float* __restrict__ rwb, const float* __restrict__ rrb)
{
    extern __shared__ float sm[];
    float* Qu = sm;                  // [i][d]  [64][68]
    float* Qv = Qu + 64 * 68;        // [d][i]  [64][68]   (transposed!)
    float* Ks = Qv + 64 * 68;        // [d][j]  [64][68]
    float* Rs = Ks + 64 * 68;        // [d][p]  [64][132]
    float* Vs = Rs + 64 * 132;       // [j][d]  [64][68]
    float* Bh = Vs + 64 * 68;        // [i][p]  [64][132]  (aliased by Ps)

    const int i0 = blockIdx.x * 64;
    const int bn = blockIdx.y;
    const int b = bn >> 4, n = bn & 15;
    const int tid = threadIdx.x;

    const float* Qg = g_Q + ((size_t)bn * QLEN + i0) * DH;
    const float* Kg = g_K + (size_t)bn * KLEN * DH;
    const float* Vg = g_V + (size_t)bn * KLEN * DH;
    const float* Rg = g_R + (size_t)n * KLEN * DH;

    // Load Q tile, fold biases and softmax scale. Qv stored transposed [d][i].
    for (int vv = tid; vv < 64 * 64 / 4; vv += 256) {
        int idx = vv * 4, i = idx >> 6, d = idx & 63;
        float4 q  = *(const float4*)(Qg + i * DH + d);
        float4 u  = *(const float4*)(rwb + n * DH + d);
        float4 vb = *(const float4*)(rrb + n * DH + d);
        Qu[i*68+d+0] = (q.x+u.x)*SCALE;  Qu[i*68+d+1] = (q.y+u.y)*SCALE;
        Qu[i*68+d+2] = (q.z+u.z)*SCALE;  Qu[i*68+d+3] = (q.w+u.w)*SCALE;
        Qv[(d+0)*68+i] = (q.x+vb.x)*SCALE; Qv[(d+1)*68+i] = (q.y+vb.y)*SCALE;
        Qv[(d+2)*68+i] = (q.z+vb.z)*SCALE; Qv[(d+3)*68+i] = (q.w+vb.w)*SCALE;
    }

    const int il = tid >> 2;     // local query row (stage2/softmax/PV mapping)
    const int qd = tid & 3;      // quad member
    const int jb = qd * 16;      // 16-wide j segment for scores
    const int d0 = qd * 16;      // 16-wide d segment for output
    const int ig = i0 + il;

    const int tr1 = tid >> 4;    // stage1 mapping: 4 i-rows
    const int tc1 = tid & 15;    //                 8 p-cols

    float m = -1e30f, l = 0.f;
    float O[16];
#pragma unroll
    for (int x = 0; x < 16; x++) O[x] = 0.f;

    const int njt = (MLEN + i0 + 63) / 64 + 1;   // causal j-tile count

    for (int jt = 0; jt < njt; jt++) {
        const int j0 = jt * 64;
        const int rbase = j0 - i0 + (QLEN - 64);  // >= 0 always
        __syncthreads();
        // K (transposed to [d][j]) and V tiles
        for (int vv = tid; vv < 64 * 64 / 4; vv += 256) {
            int idx = vv * 4, j = idx >> 6, d = idx & 63;
            float4 kv = *(const float4*)(Kg + (size_t)(j0 + j) * DH + d);
            Ks[(d+0)*68+j] = kv.x; Ks[(d+1)*68+j] = kv.y;
            Ks[(d+2)*68+j] = kv.z; Ks[(d+3)*68+j] = kv.w;
            float4 vvv = *(const float4*)(Vg + (size_t)(j0 + j) * DH + d);
            *(float4*)&Vs[j*68+d] = vvv;
        }
        // R slab [d][p], 128 rows starting at rbase (clamped; OOB rows masked)
        for (int vv = tid; vv < 128 * 64 / 4; vv += 256) {
            int idx = vv * 4, rr = idx >> 6, d = idx & 63;
            int row = rbase + rr; row = row > KLEN - 1 ? KLEN - 1 : row;
            float4 rv = *(const float4*)(Rg + (size_t)row * DH + d);
            Rs[(d+0)*132+rr] = rv.x; Rs[(d+1)*132+rr] = rv.y;
            Rs[(d+2)*132+rr] = rv.z; Rs[(d+3)*132+rr] = rv.w;
        }
        __syncthreads();

        // ---- stage1: Bh[i][p] = sum_d Qv[d][i] * Rs[d][p], 4x8 per thread
        {
            float acc[4][8];
#pragma unroll
            for (int ii = 0; ii < 4; ii++)
#pragma unroll
                for (int pp = 0; pp < 8; pp++) acc[ii][pp] = 0.f;
#pragma unroll 4
            for (int d = 0; d < 64; d++) {
                float a[4], bb[8];
                *(float4*)(a)      = *(const float4*)&Qv[d*68 + tr1*4];
                *(float4*)(bb)     = *(const float4*)&Rs[d*132 + tc1*8];
                *(float4*)(bb + 4) = *(const float4*)&Rs[d*132 + tc1*8 + 4];
#pragma unroll
                for (int ii = 0; ii < 4; ii++)
#pragma unroll
                    for (int pp = 0; pp < 8; pp++) acc[ii][pp] += a[ii] * bb[pp];
            }
#pragma unroll
            for (int ii = 0; ii < 4; ii++) {
                *(float4*)&Bh[(tr1*4+ii)*132 + tc1*8]     = *(float4*)&acc[ii][0];
                *(float4*)&Bh[(tr1*4+ii)*132 + tc1*8 + 4] = *(float4*)&acc[ii][4];
            }
        }
        __syncthreads();

        // ---- stage2: S[x] = Qu_il . K_(jb+x)
        float S[16];
#pragma unroll
        for (int x = 0; x < 16; x++) S[x] = 0.f;
        const float* qup = Qu + il * 68;
#pragma unroll 4
        for (int d = 0; d < 64; d++) {
            float qu = qup[d];
            const float* kp = Ks + d * 68 + jb;
#pragma unroll
            for (int x = 0; x < 16; x++) S[x] += qu * kp[x];
        }
        // rel-shift gather of BDhat: p = (jb+x) + 63 - il
        {
            const float* bh = Bh + il * 132 + (jb + 63 - il);
#pragma unroll
            for (int x = 0; x < 16; x++) S[x] += bh[x];
        }

        // Mask + online softmax (quad-local)
        float tmax = -1e30f;
#pragma unroll
        for (int x = 0; x < 16; x++) {
            if (j0 + jb + x > MLEN + ig) S[x] = -1e30f;
            tmax = fmaxf(tmax, S[x]);
        }
        tmax = fmaxf(tmax, __shfl_xor_sync(0xffffffffu, tmax, 1));
        tmax = fmaxf(tmax, __shfl_xor_sync(0xffffffffu, tmax, 2));
        float mnew = fmaxf(m, tmax);
        float corr = __expf(m - mnew);
        float ps = 0.f;
#pragma unroll
        for (int x = 0; x < 16; x++) { float p = __expf(S[x] - mnew); S[x] = p; ps += p; }
        ps += __shfl_xor_sync(0xffffffffu, ps, 1);
        ps += __shfl_xor_sync(0xffffffffu, ps, 2);
        l = l * corr + ps;
        m = mnew;
#pragma unroll
        for (int x = 0; x < 16; x++) O[x] *= corr;

        // publish P row segment into Bh (=Ps), then accumulate P @ V.
        float* Ps = Bh;
        __syncwarp();   // all quad reads of Bh row il complete before overwrite
#pragma unroll
        for (int x = 0; x < 16; x += 4)
            *(float4*)&Ps[il*132 + jb + x] = make_float4(S[x], S[x+1], S[x+2], S[x+3]);
        __syncwarp();
#pragma unroll 2
        for (int j = 0; j < 64; j++) {
            float p = Ps[il*132 + j];
            const float* vp = Vs + j * 68 + d0;
#pragma unroll
            for (int x = 0; x < 16; x++) O[x] += p * vp[x];
        }
    }

    const float inv = 1.f / l;
    float* op = g_AV + ((size_t)ig * BSZ + b) * DM + n * DH + d0;
#pragma unroll
    for (int x = 0; x < 16; x += 4)
        *(float4*)&op[x] = make_float4(O[x]*inv, O[x+1]*inv, O[x+2]*inv, O[x+3]*inv);
}

// ---------------------------------------------------------------------------
// Residual + LayerNorm: out = LN(w + attn_out) * g + b; one block per row.
// ---------------------------------------------------------------------------
__global__ void __launch_bounds__(256) ln_kernel(
    const float* __restrict__ w, const float* __restrict__ g,
    const float* __restrict__ beta, float* __restrict__ out)
{
    const int row = blockIdx.x;
    const float* ao = g_AO + (size_t)row * DM;
    const float* wr = w    + (size_t)row * DM;
    const int tid = threadIdx.x;
    float x[4];
    float s = 0.f, ss = 0.f;
#pragma unroll
    for (int v = 0; v < 4; v++) {
        int c = tid + v * 256;
        float val = wr[c] + ao[c];
        x[v] = val; s += val; ss += val * val;
    }
#pragma unroll
    for (int o = 16; o; o >>= 1) {
        s  += __shfl_xor_sync(0xffffffffu, s,  o);
        ss += __shfl_xor_sync(0xffffffffu, ss, o);
    }
    __shared__ float sA[8], sB[8];
    int wid = tid >> 5, lane = tid & 31;
    if (lane == 0) { sA[wid] = s; sB[wid] = ss; }
    __syncthreads();
    if (wid == 0) {
        s  = (lane < 8) ? sA[lane] : 0.f;
        ss = (lane < 8) ? sB[lane] : 0.f;
#pragma unroll
        for (int o = 4; o; o >>= 1) {
            s  += __shfl_xor_sync(0xffffffffu, s,  o);
            ss += __shfl_xor_sync(0xffffffffu, ss, o);
        }
        if (lane == 0) { sA[0] = s; sB[0] = ss; }
    }
    __syncthreads();
    const float mu  = sA[0] * (1.f / DM);
    const float var = sB[0] * (1.f / DM) - mu * mu;
    const float rstd = rsqrtf(var + 1e-5f);
#pragma unroll
    for (int v = 0; v < 4; v++) {
        int c = tid + v * 256;
        out[(size_t)row * DM + c] = (x[v] - mu) * rstd * g[c] + beta[c];
    }
}

extern "C" void kernel_launch(void* const* d_in, const int* in_sizes, int n_in,
                              void* d_out, int out_size)
{
    const float* w     = (const float*)d_in[0];
    const float* r     = (const float*)d_in[1];
    const float* mems  = (const float*)d_in[2];
    // d_in[3] = attn_mask: analytic (j > MLEN + i), never read
    const float* qkv_w = (const float*)d_in[4];
    const float* r_w   = (const float*)d_in[5];
    const float* o_w   = (const float*)d_in[6];
    const float* rwb   = (const float*)d_in[7];
    const float* rrb   = (const float*)d_in[8];
    const float* ln_g  = (const float*)d_in[9];
    const float* ln_b  = (const float*)d_in[10];
    float* out = (float*)d_out;

    // 1) QKV projection over concat(mems, w)
    sgemm_kernel<0><<<dim3(3072 / 128, (KLEN * BSZ) / 128), 256>>>(
        nullptr, qkv_w, w, mems, DM);
    // 2) relative-position keys
    sgemm_kernel<1><<<dim3(DM / 128, KLEN / 128), 256>>>(
        r, r_w, nullptr, nullptr, DM);
    // 3) fused attention
    const int shmem = (64 * 68 * 4 + 64 * 132 * 2) * 4;  // 137216 B
    cudaFuncSetAttribute(attn_kernel, cudaFuncAttributeMaxDynamicSharedMemorySize, shmem);
    attn_kernel<<<dim3(QLEN / 64, BSZ * NH), 256, shmem>>>(rwb, rrb);
    // 4) output projection
    sgemm_kernel<2><<<dim3(DM / 128, (QLEN * BSZ) / 128), 256>>>(
        nullptr, o_w, nullptr, nullptr, DM);
    // 5) residual + LayerNorm
    ln_kernel<<<QLEN * BSZ, 256>>>(w, ln_g, ln_b, out);
}

// round 6
// speedup vs baseline: 1.3005x; 1.1116x over previous
#include <cuda_runtime.h>
#include <math.h>

#define QLEN 1024
#define MLEN 1024
#define KLEN 2048
#define BSZ  4
#define DM   1024
#define NH   16
#define DH   64
#define SCALE 0.125f

// Scratch (device globals; no allocation allowed)
__device__ float g_Q [(size_t)BSZ*NH*QLEN*DH];   // [b][n][i][d]
__device__ float g_K [(size_t)BSZ*NH*KLEN*DH];   // [b][n][j][d]
__device__ float g_V [(size_t)BSZ*NH*KLEN*DH];   // [b][n][j][d]
__device__ float g_R [(size_t)NH*KLEN*DH];       // [n][p][d]
__device__ float g_AV[(size_t)QLEN*BSZ*DM];      // [i][b][n*64+d]
__device__ float g_AO[(size_t)QLEN*BSZ*DM];      // [i][b][c]

// ---------------------------------------------------------------------------
// Generic C = A @ B^T SGEMM, 128x128 tile, BK=8, 256 threads, 8x8 per thread,
// with register prefetch of the next K-slab.
// ---------------------------------------------------------------------------
template<int MODE>
__global__ void __launch_bounds__(256, 2) sgemm_kernel(
    const float* __restrict__ A, const float* __restrict__ B,
    const float* __restrict__ w, const float* __restrict__ mems, int K)
{
    __shared__ float As[8][128];
    __shared__ float Bs[8][128];
    const int tid = threadIdx.x;
    const int m0 = blockIdx.y * 128;
    const int n0 = blockIdx.x * 128;
    const int lrow = tid >> 1;          // 0..127
    const int lcol = (tid & 1) * 4;     // 0 or 4

    const float* aptr;
    if (MODE == 0) {
        int grow = m0 + lrow;
        int t = grow >> 2, b = grow & 3;
        aptr = (t < MLEN) ? (mems + ((size_t)t * BSZ + b) * DM)
                          : (w    + ((size_t)(t - MLEN) * BSZ + b) * DM);
    } else if (MODE == 2) {
        aptr = g_AV + (size_t)(m0 + lrow) * K;
    } else {
        aptr = A + (size_t)(m0 + lrow) * K;
    }
    const float* bptr = B + (size_t)(n0 + lrow) * K;

    const int tr = tid >> 4;   // 0..15
    const int tc = tid & 15;   // 0..15

    float acc[8][8];
#pragma unroll
    for (int i = 0; i < 8; i++)
#pragma unroll
        for (int j = 0; j < 8; j++) acc[i][j] = 0.f;

    float4 av = *(const float4*)(aptr + lcol);
    float4 bv = *(const float4*)(bptr + lcol);

    for (int k0 = 0; k0 < K; k0 += 8) {
        As[lcol + 0][lrow] = av.x; As[lcol + 1][lrow] = av.y;
        As[lcol + 2][lrow] = av.z; As[lcol + 3][lrow] = av.w;
        Bs[lcol + 0][lrow] = bv.x; Bs[lcol + 1][lrow] = bv.y;
        Bs[lcol + 2][lrow] = bv.z; Bs[lcol + 3][lrow] = bv.w;
        __syncthreads();
        if (k0 + 8 < K) {
            av = *(const float4*)(aptr + k0 + 8 + lcol);
            bv = *(const float4*)(bptr + k0 + 8 + lcol);
        }
#pragma unroll
        for (int k = 0; k < 8; k++) {
            float a[8], bb[8];
            *(float4*)(a)      = *(const float4*)&As[k][tr * 4];
            *(float4*)(a + 4)  = *(const float4*)&As[k][tr * 4 + 64];
            *(float4*)(bb)     = *(const float4*)&Bs[k][tc * 4];
            *(float4*)(bb + 4) = *(const float4*)&Bs[k][tc * 4 + 64];
#pragma unroll
            for (int i = 0; i < 8; i++)
#pragma unroll
                for (int j = 0; j < 8; j++) acc[i][j] += a[i] * bb[j];
        }
        __syncthreads();
    }

#pragma unroll
    for (int i = 0; i < 8; i++) {
        int gr = m0 + ((i < 4) ? tr * 4 + i : 64 + tr * 4 + i - 4);
#pragma unroll
        for (int j = 0; j < 8; j++) {
            int gc = n0 + ((j < 4) ? tc * 4 + j : 64 + tc * 4 + j - 4);
            float v = acc[i][j];
            if (MODE == 0) {
                int part = gc >> 10, hn = (gc >> 6) & 15, d = gc & 63;
                int t = gr >> 2, b = gr & 3;
                if (part == 0) {
                    if (t >= MLEN)
                        g_Q[(((size_t)(b * NH + hn)) * QLEN + (t - MLEN)) * DH + d] = v;
                } else if (part == 1) {
                    g_K[(((size_t)(b * NH + hn)) * KLEN + t) * DH + d] = v;
                } else {
                    g_V[(((size_t)(b * NH + hn)) * KLEN + t) * DH + d] = v;
                }
            } else if (MODE == 1) {
                int hn = gc >> 6, d = gc & 63;
                g_R[((size_t)hn * KLEN + gr) * DH + d] = v;
            } else {
                g_AO[(size_t)gr * DM + gc] = v;
            }
        }
    }
}

// ---------------------------------------------------------------------------
// Fused attention v3.
// Identities:
//   (q_i + r_r_bias)·R_p = (q_i + r_w_bias)·R_p + (r_r_bias - r_w_bias)·R_p
//     => BD[i][p] = Bh[i][p] + c[p] with ONE Q buffer (Qt) and a 1-D c[].
//   Rel-shift slab moves by exactly 64 rows per j-tile => sliding window:
//     copy Bh[:,0:64] <- Bh[:,64:128]; compute only the new 64 columns.
// Smem 87KB -> 2 CTAs/SM. XOR swizzle (col ^ 4*((d>>2)&7)) on Qt/Ks/Rs kills
// transpose-store bank conflicts.
// ---------------------------------------------------------------------------
#define SWZ(d) ((((d) >> 2) & 7) << 2)

__device__ __forceinline__ void stage1_chunk(const float* Qt, const float* Rs,
                                             float* Bh, int tid)
{
    const int tr1 = tid >> 4;        // 16 groups of 4 i-rows
    const int tc1 = tid & 15;        // 16 groups of 4 p-cols
    float acc[4][4];
#pragma unroll
    for (int ii = 0; ii < 4; ii++)
#pragma unroll
        for (int pp = 0; pp < 4; pp++) acc[ii][pp] = 0.f;
#pragma unroll 4
    for (int d = 0; d < 64; d++) {
        const int swz = SWZ(d);
        float a[4], bb[4];
        *(float4*)a  = *(const float4*)&Qt[d * 68 + ((tr1 * 4) ^ swz)];
        *(float4*)bb = *(const float4*)&Rs[d * 68 + ((tc1 * 4) ^ swz)];
#pragma unroll
        for (int ii = 0; ii < 4; ii++)
#pragma unroll
            for (int pp = 0; pp < 4; pp++) acc[ii][pp] += a[ii] * bb[pp];
    }
#pragma unroll
    for (int ii = 0; ii < 4; ii++)
        *(float4*)&Bh[(tr1 * 4 + ii) * 132 + 64 + tc1 * 4] = *(float4*)&acc[ii][0];
}

__global__ void __launch_bounds__(256, 2) attn_kernel(
    const float* __restrict__ rwb, const float* __restrict__ rrb)
{
    extern __shared__ float sm[];
    float* Qt    = sm;               // [d][i^swz]  64*68
    float* Ks    = Qt + 64 * 68;     // [d][j^swz]  64*68
    float* Rs    = Ks + 64 * 68;     // [d][p^swz]  64*68   (aliased by Vs [j][d])
    float* Bh    = Rs + 64 * 68;     // [i][0..127] 64*132  (cols 0..63 also Ps)
    float* cs    = Bh + 64 * 132;    // [132]
    float* diffs = cs + 132;         // [64]
    float* Vs    = Rs;               // alias

    const int i0 = blockIdx.x * 64;
    const int bn = blockIdx.y;
    const int b = bn >> 4, n = bn & 15;
    const int tid = threadIdx.x;

    const float* Qg = g_Q + ((size_t)bn * QLEN + i0) * DH;
    const float* Kg = g_K + (size_t)bn * KLEN * DH;
    const float* Vg = g_V + (size_t)bn * KLEN * DH;
    const float* Rg = g_R + (size_t)n * KLEN * DH;

    // ---- prologue: Qt (transposed, swizzled, bias+scale folded), diffs
    for (int vv = tid; vv < 64 * 64 / 4; vv += 256) {
        int idx = vv * 4, i = idx >> 6, d = idx & 63;   // d 4-aligned
        float4 q = *(const float4*)(Qg + i * DH + d);
        float4 u = *(const float4*)(rwb + n * DH + d);
        int ic = i ^ SWZ(d);
        Qt[(d + 0) * 68 + ic] = (q.x + u.x) * SCALE;
        Qt[(d + 1) * 68 + ic] = (q.y + u.y) * SCALE;
        Qt[(d + 2) * 68 + ic] = (q.z + u.z) * SCALE;
        Qt[(d + 3) * 68 + ic] = (q.w + u.w) * SCALE;
    }
    if (tid < 64) diffs[tid] = (rrb[n * DH + tid] - rwb[n * DH + tid]) * SCALE;

    const int rbase0 = QLEN - 64 - i0;   // rbase of tile 0, in [0, 960]
    // prime R chunk: rows rbase0 + rr (rr in [0,64)) -> all <= 1023, no clamp
    for (int vv = tid; vv < 64 * 64 / 4; vv += 256) {
        int idx = vv * 4, rr = idx >> 6, d = idx & 63;
        float4 rv = *(const float4*)(Rg + (size_t)(rbase0 + rr) * DH + d);
        int rc = rr ^ SWZ(d);
        Rs[(d + 0) * 68 + rc] = rv.x; Rs[(d + 1) * 68 + rc] = rv.y;
        Rs[(d + 2) * 68 + rc] = rv.z; Rs[(d + 3) * 68 + rc] = rv.w;
    }
    __syncthreads();
    // prime: Bh cols [64..127] <-> R rows rbase0 + [0..63]  (pre-window)
    stage1_chunk(Qt, Rs, Bh, tid);
    if (tid < 64) {
        float c = 0.f;
#pragma unroll 8
        for (int d = 0; d < 64; d++)
            c += diffs[d] * Rs[d * 68 + (tid ^ SWZ(d))];
        cs[64 + tid] = c;
    }

    const int il = tid >> 2;     // local query row
    const int qd = tid & 3;      // quad member
    const int jb = qd * 16;      // 16-wide j segment
    const int d0 = qd * 16;      // 16-wide d segment for O
    const int ig = i0 + il;

    float m = -1e30f, l = 0.f;
    float O[16];
#pragma unroll
    for (int x = 0; x < 16; x++) O[x] = 0.f;

    const int njt = (MLEN + i0 + 63) / 64 + 1;

    for (int jt = 0; jt < njt; jt++) {
        const int j0 = jt * 64;
        const int rbase = j0 - i0 + (QLEN - 64);
        __syncthreads();   // prev PV / prime done; Bh[64..127], cs[64..127] final

        // slide the BD window: cols [0..63] <- [64..127]
        for (int vv = tid; vv < 1024; vv += 256) {
            int row = vv >> 4, cg = vv & 15;
            *(float4*)&Bh[row * 132 + cg * 4] =
                *(const float4*)&Bh[row * 132 + 64 + cg * 4];
        }
        if (tid < 64) cs[tid] = cs[64 + tid];

        // load K tile (transposed+swizzled) and next R chunk rows rbase+64+rr
        for (int vv = tid; vv < 64 * 64 / 4; vv += 256) {
            int idx = vv * 4, j = idx >> 6, d = idx & 63;
            float4 kv = *(const float4*)(Kg + (size_t)(j0 + j) * DH + d);
            int jc = j ^ SWZ(d);
            Ks[(d + 0) * 68 + jc] = kv.x; Ks[(d + 1) * 68 + jc] = kv.y;
            Ks[(d + 2) * 68 + jc] = kv.z; Ks[(d + 3) * 68 + jc] = kv.w;
        }
        for (int vv = tid; vv < 64 * 64 / 4; vv += 256) {
            int idx = vv * 4, rr = idx >> 6, d = idx & 63;
            int row = rbase + 64 + rr; if (row > KLEN - 1) row = KLEN - 1;
            float4 rv = *(const float4*)(Rg + (size_t)row * DH + d);
            int rc = rr ^ SWZ(d);
            Rs[(d + 0) * 68 + rc] = rv.x; Rs[(d + 1) * 68 + rc] = rv.y;
            Rs[(d + 2) * 68 + rc] = rv.z; Rs[(d + 3) * 68 + rc] = rv.w;
        }
        __syncthreads();   // window slid, K/R loaded

        // new BD columns [64..127] and c[64..127]
        stage1_chunk(Qt, Rs, Bh, tid);
        if (tid < 64) {
            float c = 0.f;
#pragma unroll 8
            for (int d = 0; d < 64; d++)
                c += diffs[d] * Rs[d * 68 + (tid ^ SWZ(d))];
            cs[64 + tid] = c;
        }
        __syncthreads();   // Bh/cs window complete; Rs free

        // V tile -> registers (latency overlapped with stage2)
        float4 vreg[4];
#pragma unroll
        for (int u = 0; u < 4; u++) {
            int idx = (tid + u * 256) * 4, j = idx >> 6, d = idx & 63;
            vreg[u] = *(const float4*)(Vg + (size_t)(j0 + j) * DH + d);
        }

        // stage2: S[x] = Qt_il . K_(jb+x)
        float S[16];
#pragma unroll
        for (int x = 0; x < 16; x++) S[x] = 0.f;
#pragma unroll 2
        for (int d = 0; d < 64; d++) {
            const int swz = SWZ(d);
            float qu = Qt[d * 68 + (il ^ swz)];
            const float* krow = Ks + d * 68;
#pragma unroll
            for (int u = 0; u < 4; u++) {
                float4 kk = *(const float4*)&krow[(jb + 4 * u) ^ swz];
                S[4*u+0] += qu * kk.x; S[4*u+1] += qu * kk.y;
                S[4*u+2] += qu * kk.z; S[4*u+3] += qu * kk.w;
            }
        }
        // rel-shift gather of BD + c:  p = jb + x + 63 - il  in [0,126]
        {
            const float* bh = Bh + il * 132 + (jb + 63 - il);
            const float* cc = cs + (jb + 63 - il);
#pragma unroll
            for (int x = 0; x < 16; x++) S[x] += bh[x] + cc[x];
        }

        // mask + online softmax (quad-local)
        float tmax = -1e30f;
#pragma unroll
        for (int x = 0; x < 16; x++) {
            if (j0 + jb + x > MLEN + ig) S[x] = -1e30f;
            tmax = fmaxf(tmax, S[x]);
        }
        tmax = fmaxf(tmax, __shfl_xor_sync(0xffffffffu, tmax, 1));
        tmax = fmaxf(tmax, __shfl_xor_sync(0xffffffffu, tmax, 2));
        float mnew = fmaxf(m, tmax);
        float corr = __expf(m - mnew);
        float ps = 0.f;
#pragma unroll
        for (int x = 0; x < 16; x++) { float p = __expf(S[x] - mnew); S[x] = p; ps += p; }
        ps += __shfl_xor_sync(0xffffffffu, ps, 1);
        ps += __shfl_xor_sync(0xffffffffu, ps, 2);
        l = l * corr + ps;
        m = mnew;
#pragma unroll
        for (int x = 0; x < 16; x++) O[x] *= corr;

        // publish P into Bh cols [0..63] (row il touched only by its own warp)
        __syncwarp();
#pragma unroll
        for (int x = 0; x < 16; x += 4)
            *(float4*)&Bh[il * 132 + jb + x] =
                make_float4(S[x], S[x+1], S[x+2], S[x+3]);

        // store V tile (Vs aliases Rs; Rs reads finished at last sync)
#pragma unroll
        for (int u = 0; u < 4; u++) {
            int idx = (tid + u * 256) * 4, j = idx >> 6, d = idx & 63;
            *(float4*)&Vs[j * 68 + d] = vreg[u];
        }
        __syncthreads();   // Vs ready, P rows written

        // PV: O[x] += P[il][j] * V[j][d0+x]
#pragma unroll 2
        for (int j = 0; j < 64; j++) {
            float p = Bh[il * 132 + j];
            const float* vp = Vs + j * 68 + d0;
#pragma unroll
            for (int x = 0; x < 16; x += 4) {
                float4 vv4 = *(const float4*)&vp[x];
                O[x+0] += p * vv4.x; O[x+1] += p * vv4.y;
                O[x+2] += p * vv4.z; O[x+3] += p * vv4.w;
            }
        }
    }

    const float inv = 1.f / l;
    float* op = g_AV + ((size_t)ig * BSZ + b) * DM + n * DH + d0;
#pragma unroll
    for (int x = 0; x < 16; x += 4)
        *(float4*)&op[x] = make_float4(O[x]*inv, O[x+1]*inv, O[x+2]*inv, O[x+3]*inv);
}

// ---------------------------------------------------------------------------
// Residual + LayerNorm: out = LN(w + attn_out) * g + b; one block per row.
// ---------------------------------------------------------------------------
__global__ void __launch_bounds__(256) ln_kernel(
    const float* __restrict__ w, const float* __restrict__ g,
    const float* __restrict__ beta, float* __restrict__ out)
{
    const int row = blockIdx.x;
    const float* ao = g_AO + (size_t)row * DM;
    const float* wr = w    + (size_t)row * DM;
    const int tid = threadIdx.x;
    float x[4];
    float s = 0.f, ss = 0.f;
#pragma unroll
    for (int v = 0; v < 4; v++) {
        int c = tid + v * 256;
        float val = wr[c] + ao[c];
        x[v] = val; s += val; ss += val * val;
    }
#pragma unroll
    for (int o = 16; o; o >>= 1) {
        s  += __shfl_xor_sync(0xffffffffu, s,  o);
        ss += __shfl_xor_sync(0xffffffffu, ss, o);
    }
    __shared__ float sA[8], sB[8];
    int wid = tid >> 5, lane = tid & 31;
    if (lane == 0) { sA[wid] = s; sB[wid] = ss; }
    __syncthreads();
    if (wid == 0) {
        s  = (lane < 8) ? sA[lane] : 0.f;
        ss = (lane < 8) ? sB[lane] : 0.f;
#pragma unroll
        for (int o = 4; o; o >>= 1) {
            s  += __shfl_xor_sync(0xffffffffu, s,  o);
            ss += __shfl_xor_sync(0xffffffffu, ss, o);
        }
        if (lane == 0) { sA[0] = s; sB[0] = ss; }
    }
    __syncthreads();
    const float mu  = sA[0] * (1.f / DM);
    const float var = sB[0] * (1.f / DM) - mu * mu;
    const float rstd = rsqrtf(var + 1e-5f);
#pragma unroll
    for (int v = 0; v < 4; v++) {
        int c = tid + v * 256;
        out[(size_t)row * DM + c] = (x[v] - mu) * rstd * g[c] + beta[c];
    }
}

extern "C" void kernel_launch(void* const* d_in, const int* in_sizes, int n_in,
                              void* d_out, int out_size)
{
    const float* w     = (const float*)d_in[0];
    const float* r     = (const float*)d_in[1];
    const float* mems  = (const float*)d_in[2];
    // d_in[3] = attn_mask: analytic (j > MLEN + i), never read
    const float* qkv_w = (const float*)d_in[4];
    const float* r_w   = (const float*)d_in[5];
    const float* o_w   = (const float*)d_in[6];
    const float* rwb   = (const float*)d_in[7];
    const float* rrb   = (const float*)d_in[8];
    const float* ln_g  = (const float*)d_in[9];
    const float* ln_b  = (const float*)d_in[10];
    float* out = (float*)d_out;

    // 1) QKV projection over concat(mems, w)
    sgemm_kernel<0><<<dim3(3072 / 128, (KLEN * BSZ) / 128), 256>>>(
        nullptr, qkv_w, w, mems, DM);
    // 2) relative-position keys
    sgemm_kernel<1><<<dim3(DM / 128, KLEN / 128), 256>>>(
        r, r_w, nullptr, nullptr, DM);
    // 3) fused attention
    const int shmem = (64 * 68 * 3 + 64 * 132 + 132 + 64) * 4;  // 86800 B
    cudaFuncSetAttribute(attn_kernel, cudaFuncAttributeMaxDynamicSharedMemorySize, shmem);
    attn_kernel<<<dim3(QLEN / 64, BSZ * NH), 256, shmem>>>(rwb, rrb);
    // 4) output projection
    sgemm_kernel<2><<<dim3(DM / 128, (QLEN * BSZ) / 128), 256>>>(
        nullptr, o_w, nullptr, nullptr, DM);
    // 5) residual + LayerNorm
    ln_kernel<<<QLEN * BSZ, 256>>>(w, ln_g, ln_b, out);
}

// round 7
// speedup vs baseline: 2.5314x; 1.9465x over previous
#include <cuda_runtime.h>
#include <math.h>

#define QLEN 1024
#define MLEN 1024
#define KLEN 2048
#define BSZ  4
#define DM   1024
#define NH   16
#define DH   64
#define SCALE 0.125f

// Scratch (device globals; no allocation allowed)
__device__ float g_Q [(size_t)BSZ*NH*QLEN*DH];   // [b][n][i][d]
__device__ float g_K [(size_t)BSZ*NH*KLEN*DH];   // [b][n][j][d]
__device__ float g_V [(size_t)BSZ*NH*KLEN*DH];   // [b][n][j][d]
__device__ float g_R [(size_t)NH*KLEN*DH];       // [n][p][d]
__device__ float g_AV[(size_t)QLEN*BSZ*DM];      // [i][b][n*64+d]
__device__ float g_AO[(size_t)QLEN*BSZ*DM];      // [i][b][c]

// ---------------------------------------------------------------------------
// Generic C = A @ B^T SGEMM, 128x128 tile, BK=8, 256 threads, 8x8 per thread,
// with register prefetch of the next K-slab.
// ---------------------------------------------------------------------------
template<int MODE>
__global__ void __launch_bounds__(256, 2) sgemm_kernel(
    const float* __restrict__ A, const float* __restrict__ B,
    const float* __restrict__ w, const float* __restrict__ mems, int K)
{
    __shared__ float As[8][128];
    __shared__ float Bs[8][128];
    const int tid = threadIdx.x;
    const int m0 = blockIdx.y * 128;
    const int n0 = blockIdx.x * 128;
    const int lrow = tid >> 1;          // 0..127
    const int lcol = (tid & 1) * 4;     // 0 or 4

    const float* aptr;
    if (MODE == 0) {
        int grow = m0 + lrow;
        int t = grow >> 2, b = grow & 3;
        aptr = (t < MLEN) ? (mems + ((size_t)t * BSZ + b) * DM)
                          : (w    + ((size_t)(t - MLEN) * BSZ + b) * DM);
    } else if (MODE == 2) {
        aptr = g_AV + (size_t)(m0 + lrow) * K;
    } else {
        aptr = A + (size_t)(m0 + lrow) * K;
    }
    const float* bptr = B + (size_t)(n0 + lrow) * K;

    const int tr = tid >> 4;   // 0..15
    const int tc = tid & 15;   // 0..15

    float acc[8][8];
#pragma unroll
    for (int i = 0; i < 8; i++)
#pragma unroll
        for (int j = 0; j < 8; j++) acc[i][j] = 0.f;

    float4 av = *(const float4*)(aptr + lcol);
    float4 bv = *(const float4*)(bptr + lcol);

    for (int k0 = 0; k0 < K; k0 += 8) {
        As[lcol + 0][lrow] = av.x; As[lcol + 1][lrow] = av.y;
        As[lcol + 2][lrow] = av.z; As[lcol + 3][lrow] = av.w;
        Bs[lcol + 0][lrow] = bv.x; Bs[lcol + 1][lrow] = bv.y;
        Bs[lcol + 2][lrow] = bv.z; Bs[lcol + 3][lrow] = bv.w;
        __syncthreads();
        if (k0 + 8 < K) {
            av = *(const float4*)(aptr + k0 + 8 + lcol);
            bv = *(const float4*)(bptr + k0 + 8 + lcol);
        }
#pragma unroll
        for (int k = 0; k < 8; k++) {
            float a[8], bb[8];
            *(float4*)(a)      = *(const float4*)&As[k][tr * 4];
            *(float4*)(a + 4)  = *(const float4*)&As[k][tr * 4 + 64];
            *(float4*)(bb)     = *(const float4*)&Bs[k][tc * 4];
            *(float4*)(bb + 4) = *(const float4*)&Bs[k][tc * 4 + 64];
#pragma unroll
            for (int i = 0; i < 8; i++)
#pragma unroll
                for (int j = 0; j < 8; j++) acc[i][j] += a[i] * bb[j];
        }
        __syncthreads();
    }

#pragma unroll
    for (int i = 0; i < 8; i++) {
        int gr = m0 + ((i < 4) ? tr * 4 + i : 64 + tr * 4 + i - 4);
#pragma unroll
        for (int j = 0; j < 8; j++) {
            int gc = n0 + ((j < 4) ? tc * 4 + j : 64 + tc * 4 + j - 4);
            float v = acc[i][j];
            if (MODE == 0) {
                int part = gc >> 10, hn = (gc >> 6) & 15, d = gc & 63;
                int t = gr >> 2, b = gr & 3;
                if (part == 0) {
                    if (t >= MLEN)
                        g_Q[(((size_t)(b * NH + hn)) * QLEN + (t - MLEN)) * DH + d] = v;
                } else if (part == 1) {
                    g_K[(((size_t)(b * NH + hn)) * KLEN + t) * DH + d] = v;
                } else {
                    g_V[(((size_t)(b * NH + hn)) * KLEN + t) * DH + d] = v;
                }
            } else if (MODE == 1) {
                int hn = gc >> 6, d = gc & 63;
                g_R[((size_t)hn * KLEN + gr) * DH + d] = v;
            } else {
                g_AO[(size_t)gr * DM + gc] = v;
            }
        }
    }
}

// ---------------------------------------------------------------------------
// Fused attention v4: 4x4 register blocking, stage1+stage2 fused in one
// d-loop (shared A-operand Qt), distributed c[p] GEMV, sliding BD window.
// Thread (tr,tc): rows i = tr*4..+3, cols j/d = tc*4..+3. Row softmax stats
// via 16-lane shuffles (xor 1,2,4,8) within the tr half-warp group.
// ---------------------------------------------------------------------------
#define SWZ(d) ((((d) >> 2) & 7) << 2)

__global__ void __launch_bounds__(256, 2) attn_kernel(
    const float* __restrict__ rwb, const float* __restrict__ rrb)
{
    extern __shared__ float sm[];
    float* Qt    = sm;               // [d][i^swz]  64*68
    float* Ks    = Qt + 64 * 68;     // [d][j^swz]  64*68
    float* Rs    = Ks + 64 * 68;     // [d][p^swz]  64*68   (aliased by Vs [j][d])
    float* Bh    = Rs + 64 * 68;     // [i][0..127] 64*132  (cols 0..63 also Ps)
    float* cs    = Bh + 64 * 132;    // [132]
    float* diffs = cs + 132;         // [64]
    float* Vs    = Rs;               // alias

    const int i0 = blockIdx.x * 64;
    const int bn = blockIdx.y;
    const int b = bn >> 4, n = bn & 15;
    const int tid = threadIdx.x;
    const int tr = tid >> 4;     // 0..15 : i rows tr*4..+3
    const int tc = tid & 15;     // 0..15 : j / d cols tc*4..+3

    const float* Qg = g_Q + ((size_t)bn * QLEN + i0) * DH;
    const float* Kg = g_K + (size_t)bn * KLEN * DH;
    const float* Vg = g_V + (size_t)bn * KLEN * DH;
    const float* Rg = g_R + (size_t)n * KLEN * DH;

    // ---- prologue: Qt (transposed, swizzled, bias+scale folded), diffs
    for (int vv = tid; vv < 64 * 64 / 4; vv += 256) {
        int idx = vv * 4, i = idx >> 6, d = idx & 63;   // d 4-aligned
        float4 q = *(const float4*)(Qg + i * DH + d);
        float4 u = *(const float4*)(rwb + n * DH + d);
        int ic = i ^ SWZ(d);
        Qt[(d + 0) * 68 + ic] = (q.x + u.x) * SCALE;
        Qt[(d + 1) * 68 + ic] = (q.y + u.y) * SCALE;
        Qt[(d + 2) * 68 + ic] = (q.z + u.z) * SCALE;
        Qt[(d + 3) * 68 + ic] = (q.w + u.w) * SCALE;
    }
    if (tid < 64) diffs[tid] = (rrb[n * DH + tid] - rwb[n * DH + tid]) * SCALE;

    const int rbase0 = QLEN - 64 - i0;   // rbase of tile 0, in [0, 960]
    for (int vv = tid; vv < 64 * 64 / 4; vv += 256) {
        int idx = vv * 4, rr = idx >> 6, d = idx & 63;
        float4 rv = *(const float4*)(Rg + (size_t)(rbase0 + rr) * DH + d);
        int rc = rr ^ SWZ(d);
        Rs[(d + 0) * 68 + rc] = rv.x; Rs[(d + 1) * 68 + rc] = rv.y;
        Rs[(d + 2) * 68 + rc] = rv.z; Rs[(d + 3) * 68 + rc] = rv.w;
    }
    __syncthreads();

    // ---- prime: Bh cols [64..127] = Qt . Rs(prime chunk); cs[64..127]
    {
        float acc[4][4];
#pragma unroll
        for (int ii = 0; ii < 4; ii++)
#pragma unroll
            for (int jj = 0; jj < 4; jj++) acc[ii][jj] = 0.f;
#pragma unroll 4
        for (int d = 0; d < 64; d++) {
            const int swz = SWZ(d);
            float4 a = *(const float4*)&Qt[d * 68 + ((tr * 4) ^ swz)];
            float4 r = *(const float4*)&Rs[d * 68 + ((tc * 4) ^ swz)];
            float av[4] = {a.x, a.y, a.z, a.w};
            float rv[4] = {r.x, r.y, r.z, r.w};
#pragma unroll
            for (int ii = 0; ii < 4; ii++)
#pragma unroll
                for (int jj = 0; jj < 4; jj++) acc[ii][jj] += av[ii] * rv[jj];
        }
#pragma unroll
        for (int ii = 0; ii < 4; ii++)
            *(float4*)&Bh[(tr * 4 + ii) * 132 + 64 + tc * 4] = *(float4*)&acc[ii][0];
        // cs: distributed GEMV, 4 threads per p
        int p = tid >> 2, seg = (tid & 3) * 16;
        float c = 0.f;
#pragma unroll 4
        for (int d = seg; d < seg + 16; d++)
            c += diffs[d] * Rs[d * 68 + (p ^ SWZ(d))];
        c += __shfl_xor_sync(0xffffffffu, c, 1);
        c += __shfl_xor_sync(0xffffffffu, c, 2);
        if ((tid & 3) == 0) cs[64 + p] = c;
    }

    float m[4], l[4], O[4][4];
#pragma unroll
    for (int ii = 0; ii < 4; ii++) {
        m[ii] = -1e30f; l[ii] = 0.f;
#pragma unroll
        for (int dd = 0; dd < 4; dd++) O[ii][dd] = 0.f;
    }

    const int njt = (MLEN + i0 + 63) / 64 + 1;

    for (int jt = 0; jt < njt; jt++) {
        const int j0 = jt * 64;
        const int rbase = j0 - i0 + (QLEN - 64);
        __syncthreads();   // prev PV done; Bh[64..127], cs[64..127] final

        // slide BD window: cols [0..63] <- [64..127]
        for (int vv = tid; vv < 1024; vv += 256) {
            int row = vv >> 4, cg = vv & 15;
            *(float4*)&Bh[row * 132 + cg * 4] =
                *(const float4*)&Bh[row * 132 + 64 + cg * 4];
        }
        if (tid < 64) cs[tid] = cs[64 + tid];

        // load K tile and next R chunk (rows rbase+64+rr)
        for (int vv = tid; vv < 64 * 64 / 4; vv += 256) {
            int idx = vv * 4, j = idx >> 6, d = idx & 63;
            float4 kv = *(const float4*)(Kg + (size_t)(j0 + j) * DH + d);
            int jc = j ^ SWZ(d);
            Ks[(d + 0) * 68 + jc] = kv.x; Ks[(d + 1) * 68 + jc] = kv.y;
            Ks[(d + 2) * 68 + jc] = kv.z; Ks[(d + 3) * 68 + jc] = kv.w;
        }
        for (int vv = tid; vv < 64 * 64 / 4; vv += 256) {
            int idx = vv * 4, rr = idx >> 6, d = idx & 63;
            int row = rbase + 64 + rr; if (row > KLEN - 1) row = KLEN - 1;
            float4 rv = *(const float4*)(Rg + (size_t)row * DH + d);
            int rc = rr ^ SWZ(d);
            Rs[(d + 0) * 68 + rc] = rv.x; Rs[(d + 1) * 68 + rc] = rv.y;
            Rs[(d + 2) * 68 + rc] = rv.z; Rs[(d + 3) * 68 + rc] = rv.w;
        }
        // prefetch V tile into registers (latency spans two barriers)
        float4 vreg[4];
#pragma unroll
        for (int u = 0; u < 4; u++) {
            int idx = (tid + u * 256) * 4, j = idx >> 6, d = idx & 63;
            vreg[u] = *(const float4*)(Vg + (size_t)(j0 + j) * DH + d);
        }
        __syncthreads();   // window slid, K/R loaded

        // ---- fused stage1+2: acc_s = Qt.K, acc_bd = Qt.R  (32 FMA / 3 LDS.128)
        float as4[4][4], ab4[4][4];
#pragma unroll
        for (int ii = 0; ii < 4; ii++)
#pragma unroll
            for (int jj = 0; jj < 4; jj++) { as4[ii][jj] = 0.f; ab4[ii][jj] = 0.f; }
#pragma unroll 4
        for (int d = 0; d < 64; d++) {
            const int swz = SWZ(d);
            float4 a = *(const float4*)&Qt[d * 68 + ((tr * 4) ^ swz)];
            float4 k = *(const float4*)&Ks[d * 68 + ((tc * 4) ^ swz)];
            float4 r = *(const float4*)&Rs[d * 68 + ((tc * 4) ^ swz)];
            float av[4] = {a.x, a.y, a.z, a.w};
            float kv[4] = {k.x, k.y, k.z, k.w};
            float rv[4] = {r.x, r.y, r.z, r.w};
#pragma unroll
            for (int ii = 0; ii < 4; ii++)
#pragma unroll
                for (int jj = 0; jj < 4; jj++) {
                    as4[ii][jj] += av[ii] * kv[jj];
                    ab4[ii][jj] += av[ii] * rv[jj];
                }
        }
#pragma unroll
        for (int ii = 0; ii < 4; ii++)
            *(float4*)&Bh[(tr * 4 + ii) * 132 + 64 + tc * 4] = *(float4*)&ab4[ii][0];
        {   // cs for new columns
            int p = tid >> 2, seg = (tid & 3) * 16;
            float c = 0.f;
#pragma unroll 4
            for (int d = seg; d < seg + 16; d++)
                c += diffs[d] * Rs[d * 68 + (p ^ SWZ(d))];
            c += __shfl_xor_sync(0xffffffffu, c, 1);
            c += __shfl_xor_sync(0xffffffffu, c, 2);
            if ((tid & 3) == 0) cs[64 + p] = c;
        }
        __syncthreads();   // Bh/cs window complete; Rs free

        // store V tile (Vs aliases Rs)
#pragma unroll
        for (int u = 0; u < 4; u++) {
            int idx = (tid + u * 256) * 4, j = idx >> 6, d = idx & 63;
            *(float4*)&Vs[j * 68 + d] = vreg[u];
        }

        // ---- gather rel-shifted BD + c, mask, online softmax
        float S[4][4];
#pragma unroll
        for (int ii = 0; ii < 4; ii++) {
            const int i = tr * 4 + ii;
            const float* bh = Bh + i * 132;
#pragma unroll
            for (int jj = 0; jj < 4; jj++) {
                int pl = tc * 4 + jj + 63 - i;
                S[ii][jj] = as4[ii][jj] + bh[pl] + cs[pl];
            }
        }
        if (j0 + 63 > MLEN + i0) {
#pragma unroll
            for (int ii = 0; ii < 4; ii++) {
                const int lim = MLEN + i0 + tr * 4 + ii - j0;
#pragma unroll
                for (int jj = 0; jj < 4; jj++)
                    if (tc * 4 + jj > lim) S[ii][jj] = -1e30f;
            }
        }
#pragma unroll
        for (int ii = 0; ii < 4; ii++) {
            float t = fmaxf(fmaxf(S[ii][0], S[ii][1]), fmaxf(S[ii][2], S[ii][3]));
            t = fmaxf(t, __shfl_xor_sync(0xffffffffu, t, 1));
            t = fmaxf(t, __shfl_xor_sync(0xffffffffu, t, 2));
            t = fmaxf(t, __shfl_xor_sync(0xffffffffu, t, 4));
            t = fmaxf(t, __shfl_xor_sync(0xffffffffu, t, 8));
            float mnew = fmaxf(m[ii], t);
            float corr = __expf(m[ii] - mnew);
            float s0 = 0.f;
#pragma unroll
            for (int jj = 0; jj < 4; jj++) {
                float p = __expf(S[ii][jj] - mnew); S[ii][jj] = p; s0 += p;
            }
            s0 += __shfl_xor_sync(0xffffffffu, s0, 1);
            s0 += __shfl_xor_sync(0xffffffffu, s0, 2);
            s0 += __shfl_xor_sync(0xffffffffu, s0, 4);
            s0 += __shfl_xor_sync(0xffffffffu, s0, 8);
            l[ii] = l[ii] * corr + s0;
            m[ii] = mnew;
#pragma unroll
            for (int dd = 0; dd < 4; dd++) O[ii][dd] *= corr;
        }

        // publish P into Bh cols [0..63] (row group = 16 contiguous lanes)
        __syncwarp();
#pragma unroll
        for (int ii = 0; ii < 4; ii++)
            *(float4*)&Bh[(tr * 4 + ii) * 132 + tc * 4] = *(float4*)&S[ii][0];
        __syncthreads();   // Vs + P ready

        // ---- PV: O[ii][dd] += P[i][j] * V[j][d]
#pragma unroll 2
        for (int j = 0; j < 64; j++) {
            float4 vv4 = *(const float4*)&Vs[j * 68 + tc * 4];
            float p0 = Bh[(tr * 4 + 0) * 132 + j];
            float p1 = Bh[(tr * 4 + 1) * 132 + j];
            float p2 = Bh[(tr * 4 + 2) * 132 + j];
            float p3 = Bh[(tr * 4 + 3) * 132 + j];
            O[0][0] += p0 * vv4.x; O[0][1] += p0 * vv4.y; O[0][2] += p0 * vv4.z; O[0][3] += p0 * vv4.w;
            O[1][0] += p1 * vv4.x; O[1][1] += p1 * vv4.y; O[1][2] += p1 * vv4.z; O[1][3] += p1 * vv4.w;
            O[2][0] += p2 * vv4.x; O[2][1] += p2 * vv4.y; O[2][2] += p2 * vv4.z; O[2][3] += p2 * vv4.w;
            O[3][0] += p3 * vv4.x; O[3][1] += p3 * vv4.y; O[3][2] += p3 * vv4.z; O[3][3] += p3 * vv4.w;
        }
    }

#pragma unroll
    for (int ii = 0; ii < 4; ii++) {
        const float inv = 1.f / l[ii];
        const int ig = i0 + tr * 4 + ii;
        float* op = g_AV + ((size_t)ig * BSZ + b) * DM + n * DH + tc * 4;
        *(float4*)op = make_float4(O[ii][0]*inv, O[ii][1]*inv, O[ii][2]*inv, O[ii][3]*inv);
    }
}

// ---------------------------------------------------------------------------
// Residual + LayerNorm: out = LN(w + attn_out) * g + b; one block per row.
// ---------------------------------------------------------------------------
__global__ void __launch_bounds__(256) ln_kernel(
    const float* __restrict__ w, const float* __restrict__ g,
    const float* __restrict__ beta, float* __restrict__ out)
{
    const int row = blockIdx.x;
    const float* ao = g_AO + (size_t)row * DM;
    const float* wr = w    + (size_t)row * DM;
    const int tid = threadIdx.x;
    float x[4];
    float s = 0.f, ss = 0.f;
#pragma unroll
    for (int v = 0; v < 4; v++) {
        int c = tid + v * 256;
        float val = wr[c] + ao[c];
        x[v] = val; s += val; ss += val * val;
    }
#pragma unroll
    for (int o = 16; o; o >>= 1) {
        s  += __shfl_xor_sync(0xffffffffu, s,  o);
        ss += __shfl_xor_sync(0xffffffffu, ss, o);
    }
    __shared__ float sA[8], sB[8];
    int wid = tid >> 5, lane = tid & 31;
    if (lane == 0) { sA[wid] = s; sB[wid] = ss; }
    __syncthreads();
    if (wid == 0) {
        s  = (lane < 8) ? sA[lane] : 0.f;
        ss = (lane < 8) ? sB[lane] : 0.f;
#pragma unroll
        for (int o = 4; o; o >>= 1) {
            s  += __shfl_xor_sync(0xffffffffu, s,  o);
            ss += __shfl_xor_sync(0xffffffffu, ss, o);
        }
        if (lane == 0) { sA[0] = s; sB[0] = ss; }
    }
    __syncthreads();
    const float mu  = sA[0] * (1.f / DM);
    const float var = sB[0] * (1.f / DM) - mu * mu;
    const float rstd = rsqrtf(var + 1e-5f);
#pragma unroll
    for (int v = 0; v < 4; v++) {
        int c = tid + v * 256;
        out[(size_t)row * DM + c] = (x[v] - mu) * rstd * g[c] + beta[c];
    }
}

extern "C" void kernel_launch(void* const* d_in, const int* in_sizes, int n_in,
                              void* d_out, int out_size)
{
    const float* w     = (const float*)d_in[0];
    const float* r     = (const float*)d_in[1];
    const float* mems  = (const float*)d_in[2];
    // d_in[3] = attn_mask: analytic (j > MLEN + i), never read
    const float* qkv_w = (const float*)d_in[4];
    const float* r_w   = (const float*)d_in[5];
    const float* o_w   = (const float*)d_in[6];
    const float* rwb   = (const float*)d_in[7];
    const float* rrb   = (const float*)d_in[8];
    const float* ln_g  = (const float*)d_in[9];
    const float* ln_b  = (const float*)d_in[10];
    float* out = (float*)d_out;

    // 1) QKV projection over concat(mems, w)
    sgemm_kernel<0><<<dim3(3072 / 128, (KLEN * BSZ) / 128), 256>>>(
        nullptr, qkv_w, w, mems, DM);
    // 2) relative-position keys
    sgemm_kernel<1><<<dim3(DM / 128, KLEN / 128), 256>>>(
        r, r_w, nullptr, nullptr, DM);
    // 3) fused attention
    const int shmem = (64 * 68 * 3 + 64 * 132 + 132 + 64) * 4;  // 86800 B
    cudaFuncSetAttribute(attn_kernel, cudaFuncAttributeMaxDynamicSharedMemorySize, shmem);
    attn_kernel<<<dim3(QLEN / 64, BSZ * NH), 256, shmem>>>(rwb, rrb);
    // 4) output projection
    sgemm_kernel<2><<<dim3(DM / 128, (QLEN * BSZ) / 128), 256>>>(
        nullptr, o_w, nullptr, nullptr, DM);
    // 5) residual + LayerNorm
    ln_kernel<<<QLEN * BSZ, 256>>>(w, ln_g, ln_b, out);
}